// round 6
// baseline (speedup 1.0000x reference)
#include <cuda_runtime.h>
#include <math.h>
#include <stdint.h>

// Problem dimensions (fixed by the dataset)
#define SS 512   // timesteps
#define BB 128   // batch
#define DD 256   // input dim
#define HH 512   // hidden
#define GG 2048  // 4*H (gate-interleaved: col n = j*4 + gate)
#define BH (BB*HH)

// Device scratch (no runtime allocation allowed)
__device__ float g_U[HH*GG];               // interleaved U' [512][2048]
__device__ float g_WThi[GG*DD];            // W'^T hi (tf32-exact) [2048 n][256 k]
__device__ float g_WTlo[GG*DD];            // W'^T lo residual (tf32) [2048][256]
__device__ float g_bias[GG];               // interleaved bias [2048]
__device__ float g_mdhp[BH];               // tanh(alpha@A - (beta*ts)@B + theta@C)
__device__ float g_c[BH];                  // final cell state (for finalize)
__device__ float g_xw[(size_t)SS*BB*GG];   // precomputed x@W' + b  (512 MB)
__device__ float g_hT[2*HH*BB];            // double-buffered transposed h: [2][512 k][128 b]
__device__ unsigned g_ctr4[4];             // per-rowgroup barrier counters

// ---------------------------------------------------------------------------
// helpers
// ---------------------------------------------------------------------------
__device__ __forceinline__ float tf32_rna(float x) {
    float r; asm("cvt.rna.tf32.f32 %0, %1;" : "=f"(r) : "f"(x)); return r;
}
__device__ __forceinline__ void mma_tf32(float* c, uint32_t a0, uint32_t a1,
                                         uint32_t a2, uint32_t a3,
                                         uint32_t b0, uint32_t b1) {
    asm volatile("mma.sync.aligned.m16n8k8.row.col.f32.tf32.tf32.f32 "
        "{%0,%1,%2,%3}, {%4,%5,%6,%7}, {%8,%9}, {%0,%1,%2,%3};"
        : "+f"(c[0]), "+f"(c[1]), "+f"(c[2]), "+f"(c[3])
        : "r"(a0), "r"(a1), "r"(a2), "r"(a3), "r"(b0), "r"(b1));
}

// ---------------------------------------------------------------------------
// Build gate-interleaved U', bias, and tf32-split W'^T (n-major, k-contig)
// ---------------------------------------------------------------------------
__global__ void prep_weights(const float* __restrict__ Wi, const float* __restrict__ Ui, const float* __restrict__ bi,
                             const float* __restrict__ Wf, const float* __restrict__ Uf, const float* __restrict__ bf,
                             const float* __restrict__ Wc, const float* __restrict__ Uc, const float* __restrict__ bc,
                             const float* __restrict__ Wo, const float* __restrict__ Uo, const float* __restrict__ bo)
{
    int idx = blockIdx.x * blockDim.x + threadIdx.x;
    int stride = gridDim.x * blockDim.x;
    for (int i = idx; i < HH * GG; i += stride) {
        int k = i / GG;
        int n = i % GG;
        int j = n >> 2;
        int g = n & 3;
        const float* U = (g == 0) ? Ui : (g == 1) ? Uf : (g == 2) ? Uc : Uo;
        g_U[i] = U[k * HH + j];
        if (i < GG * DD) {
            int n2 = i / DD;      // interleaved col 0..2047
            int k2 = i % DD;      // 0..255
            int j2 = n2 >> 2;
            int g2 = n2 & 3;
            const float* W = (g2 == 0) ? Wi : (g2 == 1) ? Wf : (g2 == 2) ? Wc : Wo;
            float w = W[k2 * HH + j2];
            float hi = tf32_rna(w);
            g_WThi[i] = hi;
            g_WTlo[i] = tf32_rna(w - hi);
        }
        if (i < GG) {
            const float* bptr = (g == 0) ? bi : (g == 1) ? bf : (g == 2) ? bc : bo;
            g_bias[i] = bptr[j];
        }
    }
}

// ---------------------------------------------------------------------------
// mdhp = tanh(alpha @ A - (beta*tspan) @ B + theta @ C)   [B,H]
// ---------------------------------------------------------------------------
__global__ void mdhp_kernel(const float* __restrict__ alpha, const float* __restrict__ beta,
                            const float* __restrict__ theta, const float* __restrict__ tspan,
                            const float* __restrict__ A, const float* __restrict__ Bm,
                            const float* __restrict__ C)
{
    int b = blockIdx.x;
    int j = threadIdx.x;   // 0..511
    __shared__ float sa[256], sb[256], st[16];
    float ts = tspan[b];
    if (j < 256) {
        sa[j] = alpha[b * 256 + j];
        sb[j] = beta[b * 256 + j] * ts;
    }
    if (j < 16) st[j] = theta[b * 16 + j];
    __syncthreads();
    float acc = 0.f;
    #pragma unroll 4
    for (int k = 0; k < 256; k++)
        acc += sa[k] * A[k * 512 + j] - sb[k] * Bm[k * 512 + j];
    #pragma unroll
    for (int k = 0; k < 16; k++)
        acc += st[k] * C[k * 512 + j];
    g_mdhp[b * 512 + j] = tanhf(acc);
}

// zero barrier counters + transpose h0 into g_hT buffer 0
__global__ void prep_state(const float* __restrict__ h0)
{
    int i = blockIdx.x * blockDim.x + threadIdx.x;
    if (i < 4) g_ctr4[i] = 0u;
    if (i < HH * BB) {
        int k = i >> 7;        // 0..511
        int b = i & 127;       // 0..127
        g_hT[i] = h0[b * HH + k];
    }
}

// ---------------------------------------------------------------------------
// xW GEMM on mma.sync tf32 (3x compensation):
//   g_xw[65536, 2048] = x[65536, 256] @ W'[256, 2048] + bias
// Block: 128x128 C tile, 256 threads = 8 warps (4 M x 2 N), warp tile 32x64.
// K stepped by 8. A/B hi/lo pairs stored interleaved as float2 in smem.
// ---------------------------------------------------------------------------
__global__ __launch_bounds__(256, 2) void xw_mma(const float* __restrict__ x)
{
    __shared__ __align__(16) float2 As2[128][9];   // (m, k) -> (hi, lo)
    __shared__ __align__(16) float2 Bs2[128][9];   // (n, k) -> (hi, lo)

    const int tid   = threadIdx.x;
    const int lane  = tid & 31;
    const int wid   = tid >> 5;
    const int warpM = wid & 3;          // 0..3 -> 32-row slices
    const int warpN = wid >> 2;         // 0..1 -> 64-col slices
    const int n0 = blockIdx.x * 128;
    const int m0 = blockIdx.y * 128;

    const int r = lane >> 2;            // 0..7
    const int t = lane & 3;             // 0..3

    const int lrow = tid >> 1;          // 0..127 loader row
    const int lk   = (tid & 1) * 4;     // 0 or 4

    float c[2][8][4];
    #pragma unroll
    for (int f = 0; f < 2; f++)
        #pragma unroll
        for (int nf = 0; nf < 8; nf++)
            #pragma unroll
            for (int q = 0; q < 4; q++) c[f][nf][q] = 0.f;

    // prefetch chunk 0
    float4 pa  = *(const float4*)&x[(size_t)(m0 + lrow) * DD + lk];
    float4 pbh = *(const float4*)&g_WThi[(size_t)(n0 + lrow) * DD + lk];
    float4 pbl = *(const float4*)&g_WTlo[(size_t)(n0 + lrow) * DD + lk];

    for (int k0 = 0; k0 < DD; k0 += 8) {
        // stage prefetched chunk into smem (A split hi/lo on the fly)
        {
            float av[4] = {pa.x, pa.y, pa.z, pa.w};
            float bh[4] = {pbh.x, pbh.y, pbh.z, pbh.w};
            float bl[4] = {pbl.x, pbl.y, pbl.z, pbl.w};
            #pragma unroll
            for (int j = 0; j < 4; j++) {
                float hi = tf32_rna(av[j]);
                float lo = tf32_rna(av[j] - hi);
                As2[lrow][lk + j] = make_float2(hi, lo);
                Bs2[lrow][lk + j] = make_float2(bh[j], bl[j]);
            }
        }
        __syncthreads();

        if (k0 + 8 < DD) {
            pa  = *(const float4*)&x[(size_t)(m0 + lrow) * DD + k0 + 8 + lk];
            pbh = *(const float4*)&g_WThi[(size_t)(n0 + lrow) * DD + k0 + 8 + lk];
            pbl = *(const float4*)&g_WTlo[(size_t)(n0 + lrow) * DD + k0 + 8 + lk];
        }

        // A fragments: a0(r,t) a1(r+8,t) a2(r,t+4) a3(r+8,t+4)
        uint32_t ah[2][4], al[2][4];
        #pragma unroll
        for (int f = 0; f < 2; f++) {
            #pragma unroll
            for (int j = 0; j < 4; j++) {
                int row = warpM * 32 + f * 16 + r + (j & 1) * 8;
                int kk  = t + (j >> 1) * 4;
                float2 q = As2[row][kk];
                ah[f][j] = __float_as_uint(q.x);
                al[f][j] = __float_as_uint(q.y);
            }
        }

        // per N-fragment: load B regs, 3-pass mma into both M frags
        #pragma unroll
        for (int nf = 0; nf < 8; nf++) {
            int nrow = warpN * 64 + nf * 8 + r;
            float2 q0 = Bs2[nrow][t];
            float2 q1 = Bs2[nrow][t + 4];
            uint32_t bh0 = __float_as_uint(q0.x), bl0 = __float_as_uint(q0.y);
            uint32_t bh1 = __float_as_uint(q1.x), bl1 = __float_as_uint(q1.y);
            #pragma unroll
            for (int f = 0; f < 2; f++) {
                mma_tf32(c[f][nf], ah[f][0], ah[f][1], ah[f][2], ah[f][3], bh0, bh1);
                mma_tf32(c[f][nf], ah[f][0], ah[f][1], ah[f][2], ah[f][3], bl0, bl1);
                mma_tf32(c[f][nf], al[f][0], al[f][1], al[f][2], al[f][3], bh0, bh1);
            }
        }
        __syncthreads();
    }

    // epilogue: c0(r,2t) c1(r,2t+1) c2(r+8,2t) c3(r+8,2t+1)
    #pragma unroll
    for (int f = 0; f < 2; f++) {
        int row0 = m0 + warpM * 32 + f * 16 + r;
        #pragma unroll
        for (int nf = 0; nf < 8; nf++) {
            int col = n0 + warpN * 64 + nf * 8 + 2 * t;
            float2 bb = *(const float2*)&g_bias[col];
            float2 o0 = make_float2(c[f][nf][0] + bb.x, c[f][nf][1] + bb.y);
            float2 o1 = make_float2(c[f][nf][2] + bb.x, c[f][nf][3] + bb.y);
            *(float2*)&g_xw[(size_t)row0 * GG + col]       = o0;
            *(float2*)&g_xw[(size_t)(row0 + 8) * GG + col] = o1;
        }
    }
}

// ---------------------------------------------------------------------------
// Persistent LSTM recurrence (unchanged from round 4 — proven near FFMA floor).
// ---------------------------------------------------------------------------
__global__ __launch_bounds__(512) void lstm_persist(const float* __restrict__ c0,
                                                    float* __restrict__ out)
{
    extern __shared__ __align__(16) float sm[];
    float* us   = sm;                       // [512][64]  = 128KB
    float* hsT  = sm + 512 * 64;            // [512][32]  = 64KB
    float* part = sm + 512 * 64 + 512 * 32; // [16][512]  = 32KB

    const int tid = threadIdx.x;
    const int bx  = blockIdx.x;            // 0..31 col block
    const int rg  = blockIdx.y;            // 0..3  row group
    const int n0  = bx * 64;
    const int b0  = rg * 32;

    const int g   = tid >> 7;
    const int mt  = tid & 127;
    const int mr0 = (mt & 7) * 4;
    const int mc0 = (mt >> 3) * 4;
    const int kb  = g * 128;

    const int lr  = tid & 31;
    const int lk0 = tid >> 5;

    const int pr  = tid >> 4;
    const int pj  = tid & 15;
    const int pmt = (pj << 3) | (pr >> 2);
    const int psub = (pr & 3) * 4;
    const int jglob = bx * 16 + pj;
    const int pidx = (b0 + pr) * HH + jglob;

    for (int i = tid; i < 512 * 16; i += 512) {
        int k = i >> 4, c = (i & 15) << 2;
        *(float4*)&us[k * 64 + c] = *(const float4*)&g_U[(size_t)k * GG + n0 + c];
    }

    float cr = c0[pidx];
    float mr = g_mdhp[pidx];
    __syncthreads();

    for (int t = 0; t < SS; t++) {
        const float* hbuf = g_hT + (size_t)(t & 1) * (HH * BB);
        #pragma unroll 8
        for (int it = 0; it < 32; it++) {
            int k = lk0 + it * 16;
            hsT[k * 32 + lr] = __ldcg(&hbuf[k * BB + b0 + lr]);
        }
        float4 xw4 = *(const float4*)&g_xw[((size_t)t * BB + b0 + pr) * GG + n0 + pj * 4];
        __syncthreads();

        float acc[4][4] = {};
        #pragma unroll 4
        for (int kk = 0; kk < 128; kk++) {
            int k = kb + kk;
            float4 a = *(const float4*)&hsT[k * 32 + mr0];
            float4 b = *(const float4*)&us[k * 64 + mc0];
            float av[4] = {a.x, a.y, a.z, a.w};
            float bv[4] = {b.x, b.y, b.z, b.w};
            #pragma unroll
            for (int i = 0; i < 4; i++)
                #pragma unroll
                for (int j = 0; j < 4; j++)
                    acc[i][j] = fmaf(av[i], bv[j], acc[i][j]);
        }

        #pragma unroll
        for (int i = 0; i < 4; i++)
            #pragma unroll
            for (int j = 0; j < 4; j++)
                part[(i * 4 + j) * 512 + (g << 7) + mt] = acc[i][j];
        __syncthreads();

        {
            float gq[4];
            #pragma unroll
            for (int q = 0; q < 4; q++) {
                const float* p = &part[(psub + q) * 512 + pmt];
                gq[q] = p[0] + p[128] + p[256] + p[384];
            }
            float gi = gq[0] + xw4.x;
            float gf = gq[1] + xw4.y;
            float gc = gq[2] + xw4.z;
            float go = gq[3] + xw4.w;
            float it_ = 1.f / (1.f + __expf(-gi));
            float ft  = 1.f / (1.f + __expf(-gf));
            float ch  = tanhf(gc);
            float ot  = 1.f / (1.f + __expf(-go));
            float cn  = mr * (ft * cr + it_ * ch);
            cr = cn;
            float hn = ot * tanhf(cn);
            out[(size_t)t * BH + pidx] = hn;
            g_hT[(size_t)((t + 1) & 1) * (HH * BB) + jglob * BB + b0 + pr] = hn;
        }

        __syncthreads();
        if (tid == 0) {
            __threadfence();
            atomicAdd(&g_ctr4[rg], 1u);
            unsigned target = (unsigned)(t + 1) * 32u;
            while (*(volatile unsigned*)&g_ctr4[rg] < target) { }
            __threadfence();
        }
        __syncthreads();
    }

    g_c[pidx] = cr;
}

// copy h_T (== outputs[S-1]) and c_T into the output tail
__global__ void finalize(float* __restrict__ out)
{
    int i = blockIdx.x * blockDim.x + threadIdx.x;
    if (i < BH) {
        out[(size_t)SS * BH + i]      = out[(size_t)(SS - 1) * BH + i];
        out[(size_t)SS * BH + BH + i] = g_c[i];
    }
}

// ---------------------------------------------------------------------------
extern "C" void kernel_launch(void* const* d_in, const int* in_sizes, int n_in,
                              void* d_out, int out_size)
{
    const float* x     = (const float*)d_in[0];
    const float* h0    = (const float*)d_in[1];
    const float* c0    = (const float*)d_in[2];
    const float* alpha = (const float*)d_in[3];
    const float* beta  = (const float*)d_in[4];
    const float* theta = (const float*)d_in[5];
    const float* tspan = (const float*)d_in[6];
    const float* A     = (const float*)d_in[7];
    const float* Bm    = (const float*)d_in[8];
    const float* C     = (const float*)d_in[9];
    const float* Wi = (const float*)d_in[10];
    const float* Ui = (const float*)d_in[11];
    const float* bi = (const float*)d_in[12];
    const float* Wf = (const float*)d_in[13];
    const float* Uf = (const float*)d_in[14];
    const float* bf = (const float*)d_in[15];
    const float* Wc = (const float*)d_in[16];
    const float* Uc = (const float*)d_in[17];
    const float* bc = (const float*)d_in[18];
    const float* Wo = (const float*)d_in[19];
    const float* Uo = (const float*)d_in[20];
    const float* bo = (const float*)d_in[21];
    float* out = (float*)d_out;

    const int SMEM = (512 * 64 + 512 * 32 + 16 * 512) * sizeof(float);  // 229376 B
    cudaFuncSetAttribute(lstm_persist, cudaFuncAttributeMaxDynamicSharedMemorySize, SMEM);

    prep_weights<<<1024, 256>>>(Wi, Ui, bi, Wf, Uf, bf, Wc, Uc, bc, Wo, Uo, bo);
    mdhp_kernel<<<BB, 512>>>(alpha, beta, theta, tspan, A, Bm, C);
    prep_state<<<(HH * BB + 255) / 256, 256>>>(h0);
    xw_mma<<<dim3(GG / 128, (SS * BB) / 128), 256>>>(x);
    lstm_persist<<<dim3(32, 4), 512, SMEM>>>(c0, out);
    finalize<<<(BH + 255) / 256, 256>>>(out);
}

// round 8
// speedup vs baseline: 1.9206x; 1.9206x over previous
#include <cuda_runtime.h>
#include <cuda_bf16.h>
#include <math.h>
#include <stdint.h>

// Problem dimensions (fixed by the dataset)
#define SS 512   // timesteps
#define BB 128   // batch
#define DD 256   // input dim
#define HH 512   // hidden
#define GG 2048  // 4*H (gate-interleaved: col n = j*4 + gate)
#define BH (BB*HH)

// Device scratch (no runtime allocation allowed)
__device__ float g_W[DD*GG];                 // interleaved W' [256][2048] (for FFMA xw)
__device__ float g_bias[GG];                 // interleaved bias [2048]
__device__ __nv_bfloat16 g_UThi[GG*HH];      // U'^T hi  [2048 n][512 k] bf16
__device__ __nv_bfloat16 g_UTlo[GG*HH];      // U'^T lo  [2048 n][512 k] bf16
__device__ __nv_bfloat16 g_hBhi[2*BB*HH];    // double-buffered h hi [2][128 b][512 k]
__device__ __nv_bfloat16 g_hBlo[2*BB*HH];    // double-buffered h lo
__device__ float g_mdhp[BH];                 // tanh(alpha@A - (beta*ts)@B + theta@C)
__device__ float g_c[BH];                    // final cell state (for finalize)
__device__ float g_xw[(size_t)SS*BB*GG];     // precomputed x@W' + b  (512 MB)
__device__ unsigned g_ctr4[4];               // per-rowgroup barrier counters

// ---------------------------------------------------------------------------
// helpers
// ---------------------------------------------------------------------------
__device__ __forceinline__ void mma_bf16(float* c, uint32_t a0, uint32_t a1,
                                         uint32_t a2, uint32_t a3,
                                         uint32_t b0, uint32_t b1) {
    asm volatile("mma.sync.aligned.m16n8k16.row.col.f32.bf16.bf16.f32 "
        "{%0,%1,%2,%3}, {%4,%5,%6,%7}, {%8,%9}, {%0,%1,%2,%3};"
        : "+f"(c[0]), "+f"(c[1]), "+f"(c[2]), "+f"(c[3])
        : "r"(a0), "r"(a1), "r"(a2), "r"(a3), "r"(b0), "r"(b1));
}

// ---------------------------------------------------------------------------
// Build interleaved W' (fp32, [k][n]) for xw GEMM, bf16-split U'^T ([n][k]),
// and interleaved bias.
// ---------------------------------------------------------------------------
__global__ void prep_weights(const float* __restrict__ Wi, const float* __restrict__ Ui, const float* __restrict__ bi,
                             const float* __restrict__ Wf, const float* __restrict__ Uf, const float* __restrict__ bf,
                             const float* __restrict__ Wc, const float* __restrict__ Uc, const float* __restrict__ bc,
                             const float* __restrict__ Wo, const float* __restrict__ Uo, const float* __restrict__ bo)
{
    int idx = blockIdx.x * blockDim.x + threadIdx.x;
    int stride = gridDim.x * blockDim.x;
    for (int i = idx; i < HH * GG; i += stride) {
        {   // U'^T bf16 hi/lo: i = n*512 + k
            int n = i >> 9, k = i & 511;
            int j = n >> 2, g = n & 3;
            const float* U = (g == 0) ? Ui : (g == 1) ? Uf : (g == 2) ? Uc : Uo;
            float u = U[k * HH + j];
            __nv_bfloat16 hi = __float2bfloat16(u);
            g_UThi[i] = hi;
            g_UTlo[i] = __float2bfloat16(u - __bfloat162float(hi));
        }
        if (i < DD * GG) {   // W' interleaved [k][n]
            int k = i / GG, n = i % GG;
            int j = n >> 2, g = n & 3;
            const float* W = (g == 0) ? Wi : (g == 1) ? Wf : (g == 2) ? Wc : Wo;
            g_W[i] = W[k * HH + j];
        }
        if (i < GG) {
            int j = i >> 2, g = i & 3;
            const float* bptr = (g == 0) ? bi : (g == 1) ? bf : (g == 2) ? bc : bo;
            g_bias[i] = bptr[j];
        }
    }
}

// ---------------------------------------------------------------------------
// mdhp = tanh(alpha @ A - (beta*tspan) @ B + theta @ C)   [B,H]
// ---------------------------------------------------------------------------
__global__ void mdhp_kernel(const float* __restrict__ alpha, const float* __restrict__ beta,
                            const float* __restrict__ theta, const float* __restrict__ tspan,
                            const float* __restrict__ A, const float* __restrict__ Bm,
                            const float* __restrict__ C)
{
    int b = blockIdx.x;
    int j = threadIdx.x;   // 0..511
    __shared__ float sa[256], sb[256], st[16];
    float ts = tspan[b];
    if (j < 256) {
        sa[j] = alpha[b * 256 + j];
        sb[j] = beta[b * 256 + j] * ts;
    }
    if (j < 16) st[j] = theta[b * 16 + j];
    __syncthreads();
    float acc = 0.f;
    #pragma unroll 4
    for (int k = 0; k < 256; k++)
        acc += sa[k] * A[k * 512 + j] - sb[k] * Bm[k * 512 + j];
    #pragma unroll
    for (int k = 0; k < 16; k++)
        acc += st[k] * C[k * 512 + j];
    g_mdhp[b * 512 + j] = tanhf(acc);
}

// zero barrier counters + bf16-split h0 into g_hB buffer 0
__global__ void prep_state(const float* __restrict__ h0)
{
    int i = blockIdx.x * blockDim.x + threadIdx.x;
    if (i < 4) g_ctr4[i] = 0u;
    if (i < BB * HH) {
        float v = h0[i];                       // i = b*512 + k
        __nv_bfloat16 hi = __float2bfloat16(v);
        g_hBhi[i] = hi;
        g_hBlo[i] = __float2bfloat16(v - __bfloat162float(hi));
    }
}

// ---------------------------------------------------------------------------
// xW GEMM (fp32 FFMA, proven round-4 version):
//   g_xw[65536, 2048] = x[65536, 256] @ W'[256, 2048] + bias
// 128x128 tile, BK=8, 256 threads, 8x8 register tile
// ---------------------------------------------------------------------------
__global__ __launch_bounds__(256, 2) void xw_gemm(const float* __restrict__ x)
{
    __shared__ __align__(16) float As[8][128];
    __shared__ __align__(16) float Bs[8][128];
    const int n0 = blockIdx.x * 128;
    const int m0 = blockIdx.y * 128;
    const int tid = threadIdx.x;
    const int tr = tid >> 4;
    const int tc = tid & 15;
    const int r0 = tr * 4;
    const int c0 = tc * 4;

    const int am = tid >> 1;
    const int ak = (tid & 1) * 4;
    const int bk = tid >> 5;
    const int bc = (tid & 31) * 4;

    float acc[8][8] = {};
    float4 ra, rb;

    ra = *(const float4*)&x[(size_t)(m0 + am) * DD + ak];
    rb = *(const float4*)&g_W[(size_t)bk * GG + n0 + bc];

    for (int k0 = 0; k0 < DD; k0 += 8) {
        As[ak + 0][am] = ra.x; As[ak + 1][am] = ra.y;
        As[ak + 2][am] = ra.z; As[ak + 3][am] = ra.w;
        *(float4*)&Bs[bk][bc] = rb;
        __syncthreads();

        if (k0 + 8 < DD) {
            ra = *(const float4*)&x[(size_t)(m0 + am) * DD + k0 + 8 + ak];
            rb = *(const float4*)&g_W[(size_t)(k0 + 8 + bk) * GG + n0 + bc];
        }

        #pragma unroll
        for (int kk = 0; kk < 8; kk++) {
            float4 a0 = *(const float4*)&As[kk][r0];
            float4 a1 = *(const float4*)&As[kk][r0 + 64];
            float4 b0 = *(const float4*)&Bs[kk][c0];
            float4 b1 = *(const float4*)&Bs[kk][c0 + 64];
            float av[8] = {a0.x, a0.y, a0.z, a0.w, a1.x, a1.y, a1.z, a1.w};
            float bv[8] = {b0.x, b0.y, b0.z, b0.w, b1.x, b1.y, b1.z, b1.w};
            #pragma unroll
            for (int i = 0; i < 8; i++)
                #pragma unroll
                for (int j = 0; j < 8; j++)
                    acc[i][j] = fmaf(av[i], bv[j], acc[i][j]);
        }
        __syncthreads();
    }

    float4 bb0 = *(const float4*)&g_bias[n0 + c0];
    float4 bb1 = *(const float4*)&g_bias[n0 + c0 + 64];
    #pragma unroll
    for (int i = 0; i < 8; i++) {
        int m = m0 + ((i < 4) ? (r0 + i) : (r0 + 60 + i));
        float* orow = &g_xw[(size_t)m * GG + n0];
        float4 o0 = make_float4(acc[i][0] + bb0.x, acc[i][1] + bb0.y,
                                acc[i][2] + bb0.z, acc[i][3] + bb0.w);
        float4 o1 = make_float4(acc[i][4] + bb1.x, acc[i][5] + bb1.y,
                                acc[i][6] + bb1.z, acc[i][7] + bb1.w);
        *(float4*)&orow[c0]      = o0;
        *(float4*)&orow[c0 + 64] = o1;
    }
}

// ---------------------------------------------------------------------------
// Persistent LSTM recurrence on mma.sync bf16 (2-way split, 3-term product).
// Grid: (32 col-blocks, 4 row-groups) = 128 blocks, 512 threads = 16 warps.
// Block tile: 32 batch rows x 64 interleaved gate cols (= 16 h-cols x 4 gates).
// Warp map: kseg = wid>>3 in {0,1} (K halves of 256 elems = 128 words each);
//           ow = wid&7 -> output tile m16 x n16 (mbase = (ow>>2)*16,
//           nbase = (ow&3)*16), j in {0,1} covers n16.
// smem: U'^T bf16 hi/lo [64][260w] persistent; h bf16 hi/lo [32][260w]/step;
//       partials [2][32][68] f32. Total 217088 B.
// ---------------------------------------------------------------------------
#define ROWW 260   // uint32 words per padded bf16 row (520 bf16; 256 data words)
__global__ __launch_bounds__(512) void lstm_persist(const float* __restrict__ c0,
                                                    float* __restrict__ out)
{
    extern __shared__ __align__(16) uint32_t smw[];
    uint32_t* u_hi = smw;                               // [64][260]
    uint32_t* u_lo = smw + 64 * ROWW;                   // [64][260]
    uint32_t* h_hi = smw + 2 * 64 * ROWW;               // [32][260]
    uint32_t* h_lo = smw + 2 * 64 * ROWW + 32 * ROWW;   // [32][260]
    float*    part = (float*)(smw + 2 * 64 * ROWW + 2 * 32 * ROWW); // [2][32][68]

    const int tid = threadIdx.x;
    const int bx  = blockIdx.x;            // 0..31 col block
    const int rg  = blockIdx.y;            // 0..3  row group
    const int n0  = bx * 64;               // interleaved gate-col base
    const int b0  = rg * 32;               // batch row base

    const int lane = tid & 31;
    const int wid  = tid >> 5;             // 0..15
    const int kseg  = wid >> 3;            // 0..1  K half
    const int ow    = wid & 7;             // 0..7  output warp
    const int mbase = (ow >> 2) * 16;      // 0 or 16
    const int nbase = (ow & 3) * 16;       // 0,16,32,48
    const int r  = lane >> 2;              // 0..7 (groupID)
    const int tq = lane & 3;               // 0..3 (threadID in group)

    // gate-phase mapping: 1 h-element per thread
    const int pr = tid >> 4;               // 0..31
    const int pj = tid & 15;               // 0..15
    const int jglob = bx * 16 + pj;
    const int pidx = (b0 + pr) * HH + jglob;

    // ---- load persistent U'^T slice (bf16 hi/lo) ----
    #pragma unroll
    for (int q = 0; q < 8; q++) {
        int u = tid + q * 512;              // 0..4095
        int row = u >> 6;                   // 0..63
        int c4  = u & 63;                   // uint4 index in row (0..63)
        uint4 vh = *((const uint4*)(g_UThi + (size_t)(n0 + row) * HH) + c4);
        uint4 vl = *((const uint4*)(g_UTlo + (size_t)(n0 + row) * HH) + c4);
        *(uint4*)(u_hi + row * ROWW + c4 * 4) = vh;
        *(uint4*)(u_lo + row * ROWW + c4 * 4) = vl;
    }

    float cr = c0[pidx];
    float mr = g_mdhp[pidx];
    __syncthreads();

    for (int t = 0; t < SS; t++) {
        // ---- stage h (bf16 hi/lo): 32 rows x 256 words, coalesced L2 reads ----
        const __nv_bfloat16* hbh = g_hBhi + (size_t)(t & 1) * (BB * HH);
        const __nv_bfloat16* hbl = g_hBlo + (size_t)(t & 1) * (BB * HH);
        #pragma unroll
        for (int q = 0; q < 4; q++) {
            int u = tid + q * 512;          // 0..2047
            int row = u >> 6;               // 0..31
            int c4  = u & 63;
            uint4 vh = __ldcg((const uint4*)(hbh + (size_t)(b0 + row) * HH) + c4);
            uint4 vl = __ldcg((const uint4*)(hbl + (size_t)(b0 + row) * HH) + c4);
            *(uint4*)(h_hi + row * ROWW + c4 * 4) = vh;
            *(uint4*)(h_lo + row * ROWW + c4 * 4) = vl;
        }
        float4 xw4 = *(const float4*)&g_xw[((size_t)t * BB + b0 + pr) * GG + n0 + pj * 4];
        __syncthreads();

        // ---- GEMM: warp tile m16 x n16, half the K range ----
        float c[2][4] = {};
        const int arow0 = (mbase + r) * ROWW;
        const int arow1 = (mbase + r + 8) * ROWW;
        #pragma unroll 4
        for (int ks = 0; ks < 16; ks++) {
            int kw = kseg * 128 + ks * 8 + tq;   // word offset (max 255 < 256)
            uint32_t ah0 = h_hi[arow0 + kw];
            uint32_t ah1 = h_hi[arow1 + kw];
            uint32_t ah2 = h_hi[arow0 + kw + 4];
            uint32_t ah3 = h_hi[arow1 + kw + 4];
            uint32_t al0 = h_lo[arow0 + kw];
            uint32_t al1 = h_lo[arow1 + kw];
            uint32_t al2 = h_lo[arow0 + kw + 4];
            uint32_t al3 = h_lo[arow1 + kw + 4];
            #pragma unroll
            for (int j = 0; j < 2; j++) {
                int nr = (nbase + j * 8 + r) * ROWW + kw;   // row <= 63
                uint32_t bh0 = u_hi[nr], bh1 = u_hi[nr + 4];
                uint32_t bl0 = u_lo[nr], bl1 = u_lo[nr + 4];
                mma_bf16(c[j], ah0, ah1, ah2, ah3, bh0, bh1);
                mma_bf16(c[j], ah0, ah1, ah2, ah3, bl0, bl1);
                mma_bf16(c[j], al0, al1, al2, al3, bh0, bh1);
            }
        }

        // ---- write partials (disjoint regions per warp) ----
        #pragma unroll
        for (int j = 0; j < 2; j++) {
            float* p = part + kseg * (32 * 68) + (mbase + r) * 68 + nbase + j * 8 + 2 * tq;
            *(float2*)p            = make_float2(c[j][0], c[j][1]);   // row mbase+r
            *(float2*)(p + 8 * 68) = make_float2(c[j][2], c[j][3]);   // row mbase+r+8
        }
        __syncthreads();

        // ---- reduce K-halves + gates (1 h-element per thread) ----
        {
            float4 p0 = *(const float4*)&part[pr * 68 + pj * 4];
            float4 p1 = *(const float4*)&part[32 * 68 + pr * 68 + pj * 4];
            float gi = p0.x + p1.x + xw4.x;
            float gf = p0.y + p1.y + xw4.y;
            float gc = p0.z + p1.z + xw4.z;
            float go = p0.w + p1.w + xw4.w;
            float it_ = 1.f / (1.f + __expf(-gi));
            float ft  = 1.f / (1.f + __expf(-gf));
            float ch  = tanhf(gc);
            float ot  = 1.f / (1.f + __expf(-go));
            float cn  = mr * (ft * cr + it_ * ch);
            cr = cn;
            float hn = ot * tanhf(cn);
            out[(size_t)t * BH + pidx] = hn;
            size_t nb = (size_t)((t + 1) & 1) * (BB * HH);
            __nv_bfloat16 hb = __float2bfloat16(hn);
            g_hBhi[nb + pidx] = hb;
            g_hBlo[nb + pidx] = __float2bfloat16(hn - __bfloat162float(hb));
        }

        // ---- per-rowgroup barrier (32 blocks) ----
        __syncthreads();
        if (tid == 0) {
            __threadfence();
            atomicAdd(&g_ctr4[rg], 1u);
            unsigned target = (unsigned)(t + 1) * 32u;
            while (*(volatile unsigned*)&g_ctr4[rg] < target) { }
            __threadfence();
        }
        __syncthreads();
    }

    g_c[pidx] = cr;
}

// copy h_T (== outputs[S-1]) and c_T into the output tail
__global__ void finalize(float* __restrict__ out)
{
    int i = blockIdx.x * blockDim.x + threadIdx.x;
    if (i < BH) {
        out[(size_t)SS * BH + i]      = out[(size_t)(SS - 1) * BH + i];
        out[(size_t)SS * BH + BH + i] = g_c[i];
    }
}

// ---------------------------------------------------------------------------
extern "C" void kernel_launch(void* const* d_in, const int* in_sizes, int n_in,
                              void* d_out, int out_size)
{
    const float* x     = (const float*)d_in[0];
    const float* h0    = (const float*)d_in[1];
    const float* c0    = (const float*)d_in[2];
    const float* alpha = (const float*)d_in[3];
    const float* beta  = (const float*)d_in[4];
    const float* theta = (const float*)d_in[5];
    const float* tspan = (const float*)d_in[6];
    const float* A     = (const float*)d_in[7];
    const float* Bm    = (const float*)d_in[8];
    const float* C     = (const float*)d_in[9];
    const float* Wi = (const float*)d_in[10];
    const float* Ui = (const float*)d_in[11];
    const float* bi = (const float*)d_in[12];
    const float* Wf = (const float*)d_in[13];
    const float* Uf = (const float*)d_in[14];
    const float* bf = (const float*)d_in[15];
    const float* Wc = (const float*)d_in[16];
    const float* Uc = (const float*)d_in[17];
    const float* bc = (const float*)d_in[18];
    const float* Wo = (const float*)d_in[19];
    const float* Uo = (const float*)d_in[20];
    const float* bo = (const float*)d_in[21];
    float* out = (float*)d_out;

    // smem: U hi/lo (2*64*260 w) + h hi/lo (2*32*260 w) + part (2*32*68 w)
    const int SMEM = (2 * 64 * ROWW + 2 * 32 * ROWW + 2 * 32 * 68) * 4;  // 217088 B
    cudaFuncSetAttribute(lstm_persist, cudaFuncAttributeMaxDynamicSharedMemorySize, SMEM);

    prep_weights<<<1024, 256>>>(Wi, Ui, bi, Wf, Uf, bf, Wc, Uc, bc, Wo, Uo, bo);
    mdhp_kernel<<<BB, 512>>>(alpha, beta, theta, tspan, A, Bm, C);
    prep_state<<<(BB * HH + 255) / 256, 256>>>(h0);
    xw_gemm<<<dim3(GG / 128, (SS * BB) / 128), 256>>>(x);
    lstm_persist<<<dim3(32, 4), 512, SMEM>>>(c0, out);
    finalize<<<(BH + 255) / 256, 256>>>(out);
}

// round 9
// speedup vs baseline: 2.2474x; 1.1702x over previous
#include <cuda_runtime.h>
#include <cuda_bf16.h>
#include <math.h>
#include <stdint.h>

// Problem dimensions (fixed by the dataset)
#define SS 512   // timesteps
#define BB 128   // batch
#define DD 256   // input dim
#define HH 512   // hidden
#define GG 2048  // 4*H (gate-interleaved: col n = j*4 + gate)
#define BH (BB*HH)

// Device scratch (no runtime allocation allowed)
__device__ float g_bias[GG];                 // interleaved bias [2048]
__device__ __nv_bfloat16 g_UThi[GG*HH];      // U'^T hi  [2048 n][512 k] bf16
__device__ __nv_bfloat16 g_UTlo[GG*HH];      // U'^T lo
__device__ __nv_bfloat16 g_WThi[GG*DD];      // W'^T hi  [2048 n][256 k] bf16
__device__ __nv_bfloat16 g_WTlo[GG*DD];      // W'^T lo
__device__ __nv_bfloat16 g_xhi[(size_t)SS*BB*DD];  // x hi  [65536 m][256 k] bf16
__device__ __nv_bfloat16 g_xlo[(size_t)SS*BB*DD];  // x lo
__device__ __nv_bfloat16 g_hBhi[2*BB*HH];    // double-buffered h hi [2][128 b][512 k]
__device__ __nv_bfloat16 g_hBlo[2*BB*HH];    // double-buffered h lo
__device__ float g_mdhp[BH];                 // tanh(alpha@A - (beta*ts)@B + theta@C)
__device__ float g_c[BH];                    // final cell state (for finalize)
__device__ float g_xw[(size_t)SS*BB*GG];     // precomputed x@W' + b  (512 MB)
__device__ unsigned g_ctr4[4];               // per-rowgroup barrier counters

// ---------------------------------------------------------------------------
// helpers
// ---------------------------------------------------------------------------
__device__ __forceinline__ void mma_bf16(float* c, uint32_t a0, uint32_t a1,
                                         uint32_t a2, uint32_t a3,
                                         uint32_t b0, uint32_t b1) {
    asm volatile("mma.sync.aligned.m16n8k16.row.col.f32.bf16.bf16.f32 "
        "{%0,%1,%2,%3}, {%4,%5,%6,%7}, {%8,%9}, {%0,%1,%2,%3};"
        : "+f"(c[0]), "+f"(c[1]), "+f"(c[2]), "+f"(c[3])
        : "r"(a0), "r"(a1), "r"(a2), "r"(a3), "r"(b0), "r"(b1));
}

// ---------------------------------------------------------------------------
// Build bf16-split U'^T, W'^T (both [n][k], n gate-interleaved), and bias.
// ---------------------------------------------------------------------------
__global__ void prep_weights(const float* __restrict__ Wi, const float* __restrict__ Ui, const float* __restrict__ bi,
                             const float* __restrict__ Wf, const float* __restrict__ Uf, const float* __restrict__ bf,
                             const float* __restrict__ Wc, const float* __restrict__ Uc, const float* __restrict__ bc,
                             const float* __restrict__ Wo, const float* __restrict__ Uo, const float* __restrict__ bo)
{
    int idx = blockIdx.x * blockDim.x + threadIdx.x;
    int stride = gridDim.x * blockDim.x;
    for (int i = idx; i < HH * GG; i += stride) {
        {   // U'^T bf16 hi/lo: i = n*512 + k
            int n = i >> 9, k = i & 511;
            int j = n >> 2, g = n & 3;
            const float* U = (g == 0) ? Ui : (g == 1) ? Uf : (g == 2) ? Uc : Uo;
            float u = U[k * HH + j];
            __nv_bfloat16 hi = __float2bfloat16(u);
            g_UThi[i] = hi;
            g_UTlo[i] = __float2bfloat16(u - __bfloat162float(hi));
        }
        if (i < GG * DD) {   // W'^T bf16 hi/lo: i = n*256 + k
            int n = i >> 8, k = i & 255;
            int j = n >> 2, g = n & 3;
            const float* W = (g == 0) ? Wi : (g == 1) ? Wf : (g == 2) ? Wc : Wo;
            float w = W[k * HH + j];
            __nv_bfloat16 hi = __float2bfloat16(w);
            g_WThi[i] = hi;
            g_WTlo[i] = __float2bfloat16(w - __bfloat162float(hi));
        }
        if (i < GG) {
            int j = i >> 2, g = i & 3;
            const float* bptr = (g == 0) ? bi : (g == 1) ? bf : (g == 2) ? bc : bo;
            g_bias[i] = bptr[j];
        }
    }
}

// split x into bf16 hi/lo (16.7M elements, 4 per thread)
__global__ void xsplit(const float* __restrict__ x)
{
    size_t i = (size_t)blockIdx.x * blockDim.x + threadIdx.x;   // float4 index
    float4 v = *((const float4*)x + i);
    __nv_bfloat16 h0 = __float2bfloat16(v.x);
    __nv_bfloat16 h1 = __float2bfloat16(v.y);
    __nv_bfloat16 h2 = __float2bfloat16(v.z);
    __nv_bfloat16 h3 = __float2bfloat16(v.w);
    __nv_bfloat16 l0 = __float2bfloat16(v.x - __bfloat162float(h0));
    __nv_bfloat16 l1 = __float2bfloat16(v.y - __bfloat162float(h1));
    __nv_bfloat16 l2 = __float2bfloat16(v.z - __bfloat162float(h2));
    __nv_bfloat16 l3 = __float2bfloat16(v.w - __bfloat162float(h3));
    ushort4 ph = make_ushort4(__bfloat16_as_ushort(h0), __bfloat16_as_ushort(h1),
                              __bfloat16_as_ushort(h2), __bfloat16_as_ushort(h3));
    ushort4 pl = make_ushort4(__bfloat16_as_ushort(l0), __bfloat16_as_ushort(l1),
                              __bfloat16_as_ushort(l2), __bfloat16_as_ushort(l3));
    *((ushort4*)g_xhi + i) = ph;
    *((ushort4*)g_xlo + i) = pl;
}

// ---------------------------------------------------------------------------
// mdhp = tanh(alpha @ A - (beta*tspan) @ B + theta @ C)   [B,H]
// ---------------------------------------------------------------------------
__global__ void mdhp_kernel(const float* __restrict__ alpha, const float* __restrict__ beta,
                            const float* __restrict__ theta, const float* __restrict__ tspan,
                            const float* __restrict__ A, const float* __restrict__ Bm,
                            const float* __restrict__ C)
{
    int b = blockIdx.x;
    int j = threadIdx.x;   // 0..511
    __shared__ float sa[256], sb[256], st[16];
    float ts = tspan[b];
    if (j < 256) {
        sa[j] = alpha[b * 256 + j];
        sb[j] = beta[b * 256 + j] * ts;
    }
    if (j < 16) st[j] = theta[b * 16 + j];
    __syncthreads();
    float acc = 0.f;
    #pragma unroll 4
    for (int k = 0; k < 256; k++)
        acc += sa[k] * A[k * 512 + j] - sb[k] * Bm[k * 512 + j];
    #pragma unroll
    for (int k = 0; k < 16; k++)
        acc += st[k] * C[k * 512 + j];
    g_mdhp[b * 512 + j] = tanhf(acc);
}

// zero barrier counters + bf16-split h0 into g_hB buffer 0
__global__ void prep_state(const float* __restrict__ h0)
{
    int i = blockIdx.x * blockDim.x + threadIdx.x;
    if (i < 4) g_ctr4[i] = 0u;
    if (i < BB * HH) {
        float v = h0[i];                       // i = b*512 + k
        __nv_bfloat16 hi = __float2bfloat16(v);
        g_hBhi[i] = hi;
        g_hBlo[i] = __float2bfloat16(v - __bfloat162float(hi));
    }
}

// ---------------------------------------------------------------------------
// xW GEMM on mma.sync bf16 (2-way split, 3-term product):
//   g_xw[65536, 2048] = x[65536, 256] @ W'[256, 2048] + bias
// Block: 128x128 C tile, 256 threads = 8 warps (4 M x 2 N), warp tile 32x64.
// K in 4 chunks of 64; smem rows padded to 36 words (conflict-free 4r+tq map).
// ---------------------------------------------------------------------------
#define ROWX 36   // uint32 words per padded row (32 data words = 64 bf16)
__global__ __launch_bounds__(256, 2) void xw_mma()
{
    extern __shared__ __align__(16) uint32_t xs[];
    uint32_t* a_hi = xs;                    // [128][36]
    uint32_t* a_lo = xs + 128 * ROWX;
    uint32_t* b_hi = xs + 2 * 128 * ROWX;
    uint32_t* b_lo = xs + 3 * 128 * ROWX;

    const int tid  = threadIdx.x;
    const int lane = tid & 31;
    const int wid  = tid >> 5;
    const int mbase = (wid & 3) * 32;       // 0,32,64,96
    const int nbase = (wid >> 2) * 64;      // 0,64
    const int r  = lane >> 2;               // 0..7
    const int tq = lane & 3;                // 0..3
    const int n0 = blockIdx.x * 128;
    const int m0 = blockIdx.y * 128;

    float c[2][8][4];
    #pragma unroll
    for (int f = 0; f < 2; f++)
        #pragma unroll
        for (int j = 0; j < 8; j++)
            #pragma unroll
            for (int q = 0; q < 4; q++) c[f][j][q] = 0.f;

    for (int kc = 0; kc < 4; kc++) {
        const int k0 = kc * 64;
        // load A/B 64-k chunks (bf16 hi/lo), 8 uint4 per row
        #pragma unroll
        for (int q = 0; q < 4; q++) {
            int u = tid + q * 256;          // 0..1023
            int row = u >> 3;               // 0..127
            int c4  = u & 7;                // uint4 within row
            uint4 vah = *((const uint4*)(g_xhi + (size_t)(m0 + row) * DD + k0) + c4);
            uint4 val = *((const uint4*)(g_xlo + (size_t)(m0 + row) * DD + k0) + c4);
            uint4 vbh = *((const uint4*)(g_WThi + (size_t)(n0 + row) * DD + k0) + c4);
            uint4 vbl = *((const uint4*)(g_WTlo + (size_t)(n0 + row) * DD + k0) + c4);
            *(uint4*)(a_hi + row * ROWX + c4 * 4) = vah;
            *(uint4*)(a_lo + row * ROWX + c4 * 4) = val;
            *(uint4*)(b_hi + row * ROWX + c4 * 4) = vbh;
            *(uint4*)(b_lo + row * ROWX + c4 * 4) = vbl;
        }
        __syncthreads();

        #pragma unroll
        for (int ks = 0; ks < 4; ks++) {
            const int kw = ks * 8 + tq;
            uint32_t ah[2][4], al[2][4];
            #pragma unroll
            for (int f = 0; f < 2; f++) {
                int ar0 = (mbase + f * 16 + r) * ROWX;
                int ar1 = (mbase + f * 16 + r + 8) * ROWX;
                ah[f][0] = a_hi[ar0 + kw]; ah[f][1] = a_hi[ar1 + kw];
                ah[f][2] = a_hi[ar0 + kw + 4]; ah[f][3] = a_hi[ar1 + kw + 4];
                al[f][0] = a_lo[ar0 + kw]; al[f][1] = a_lo[ar1 + kw];
                al[f][2] = a_lo[ar0 + kw + 4]; al[f][3] = a_lo[ar1 + kw + 4];
            }
            #pragma unroll
            for (int j = 0; j < 8; j++) {
                int nr = (nbase + j * 8 + r) * ROWX + kw;
                uint32_t bh0 = b_hi[nr], bh1 = b_hi[nr + 4];
                uint32_t bl0 = b_lo[nr], bl1 = b_lo[nr + 4];
                #pragma unroll
                for (int f = 0; f < 2; f++) {
                    mma_bf16(c[f][j], ah[f][0], ah[f][1], ah[f][2], ah[f][3], bh0, bh1);
                    mma_bf16(c[f][j], ah[f][0], ah[f][1], ah[f][2], ah[f][3], bl0, bl1);
                    mma_bf16(c[f][j], al[f][0], al[f][1], al[f][2], al[f][3], bh0, bh1);
                }
            }
        }
        __syncthreads();
    }

    // epilogue: c0(r,2tq) c1(r,2tq+1) c2(r+8,2tq) c3(r+8,2tq+1)
    #pragma unroll
    for (int f = 0; f < 2; f++) {
        int row0 = m0 + mbase + f * 16 + r;
        #pragma unroll
        for (int j = 0; j < 8; j++) {
            int col = n0 + nbase + j * 8 + 2 * tq;
            float2 bb = *(const float2*)&g_bias[col];
            float2 o0 = make_float2(c[f][j][0] + bb.x, c[f][j][1] + bb.y);
            float2 o1 = make_float2(c[f][j][2] + bb.x, c[f][j][3] + bb.y);
            *(float2*)&g_xw[(size_t)row0 * GG + col]       = o0;
            *(float2*)&g_xw[(size_t)(row0 + 8) * GG + col] = o1;
        }
    }
}

// ---------------------------------------------------------------------------
// Persistent LSTM recurrence on mma.sync bf16 (unchanged from round 8 — proven).
// ---------------------------------------------------------------------------
#define ROWW 260   // uint32 words per padded bf16 row (520 bf16; 256 data words)
__global__ __launch_bounds__(512) void lstm_persist(const float* __restrict__ c0,
                                                    float* __restrict__ out)
{
    extern __shared__ __align__(16) uint32_t smw[];
    uint32_t* u_hi = smw;                               // [64][260]
    uint32_t* u_lo = smw + 64 * ROWW;                   // [64][260]
    uint32_t* h_hi = smw + 2 * 64 * ROWW;               // [32][260]
    uint32_t* h_lo = smw + 2 * 64 * ROWW + 32 * ROWW;   // [32][260]
    float*    part = (float*)(smw + 2 * 64 * ROWW + 2 * 32 * ROWW); // [2][32][68]

    const int tid = threadIdx.x;
    const int bx  = blockIdx.x;            // 0..31 col block
    const int rg  = blockIdx.y;            // 0..3  row group
    const int n0  = bx * 64;               // interleaved gate-col base
    const int b0  = rg * 32;               // batch row base

    const int lane = tid & 31;
    const int wid  = tid >> 5;             // 0..15
    const int kseg  = wid >> 3;            // 0..1  K half
    const int ow    = wid & 7;             // 0..7  output warp
    const int mbase = (ow >> 2) * 16;      // 0 or 16
    const int nbase = (ow & 3) * 16;       // 0,16,32,48
    const int r  = lane >> 2;              // 0..7
    const int tq = lane & 3;               // 0..3

    const int pr = tid >> 4;               // 0..31
    const int pj = tid & 15;               // 0..15
    const int jglob = bx * 16 + pj;
    const int pidx = (b0 + pr) * HH + jglob;

    // ---- load persistent U'^T slice (bf16 hi/lo) ----
    #pragma unroll
    for (int q = 0; q < 8; q++) {
        int u = tid + q * 512;              // 0..4095
        int row = u >> 6;                   // 0..63
        int c4  = u & 63;
        uint4 vh = *((const uint4*)(g_UThi + (size_t)(n0 + row) * HH) + c4);
        uint4 vl = *((const uint4*)(g_UTlo + (size_t)(n0 + row) * HH) + c4);
        *(uint4*)(u_hi + row * ROWW + c4 * 4) = vh;
        *(uint4*)(u_lo + row * ROWW + c4 * 4) = vl;
    }

    float cr = c0[pidx];
    float mr = g_mdhp[pidx];
    __syncthreads();

    for (int t = 0; t < SS; t++) {
        const __nv_bfloat16* hbh = g_hBhi + (size_t)(t & 1) * (BB * HH);
        const __nv_bfloat16* hbl = g_hBlo + (size_t)(t & 1) * (BB * HH);
        #pragma unroll
        for (int q = 0; q < 4; q++) {
            int u = tid + q * 512;          // 0..2047
            int row = u >> 6;               // 0..31
            int c4  = u & 63;
            uint4 vh = __ldcg((const uint4*)(hbh + (size_t)(b0 + row) * HH) + c4);
            uint4 vl = __ldcg((const uint4*)(hbl + (size_t)(b0 + row) * HH) + c4);
            *(uint4*)(h_hi + row * ROWW + c4 * 4) = vh;
            *(uint4*)(h_lo + row * ROWW + c4 * 4) = vl;
        }
        float4 xw4 = *(const float4*)&g_xw[((size_t)t * BB + b0 + pr) * GG + n0 + pj * 4];
        __syncthreads();

        float c[2][4] = {};
        const int arow0 = (mbase + r) * ROWW;
        const int arow1 = (mbase + r + 8) * ROWW;
        #pragma unroll 4
        for (int ks = 0; ks < 16; ks++) {
            int kw = kseg * 128 + ks * 8 + tq;
            uint32_t ah0 = h_hi[arow0 + kw];
            uint32_t ah1 = h_hi[arow1 + kw];
            uint32_t ah2 = h_hi[arow0 + kw + 4];
            uint32_t ah3 = h_hi[arow1 + kw + 4];
            uint32_t al0 = h_lo[arow0 + kw];
            uint32_t al1 = h_lo[arow1 + kw];
            uint32_t al2 = h_lo[arow0 + kw + 4];
            uint32_t al3 = h_lo[arow1 + kw + 4];
            #pragma unroll
            for (int j = 0; j < 2; j++) {
                int nr = (nbase + j * 8 + r) * ROWW + kw;
                uint32_t bh0 = u_hi[nr], bh1 = u_hi[nr + 4];
                uint32_t bl0 = u_lo[nr], bl1 = u_lo[nr + 4];
                mma_bf16(c[j], ah0, ah1, ah2, ah3, bh0, bh1);
                mma_bf16(c[j], ah0, ah1, ah2, ah3, bl0, bl1);
                mma_bf16(c[j], al0, al1, al2, al3, bh0, bh1);
            }
        }

        #pragma unroll
        for (int j = 0; j < 2; j++) {
            float* p = part + kseg * (32 * 68) + (mbase + r) * 68 + nbase + j * 8 + 2 * tq;
            *(float2*)p            = make_float2(c[j][0], c[j][1]);
            *(float2*)(p + 8 * 68) = make_float2(c[j][2], c[j][3]);
        }
        __syncthreads();

        {
            float4 p0 = *(const float4*)&part[pr * 68 + pj * 4];
            float4 p1 = *(const float4*)&part[32 * 68 + pr * 68 + pj * 4];
            float gi = p0.x + p1.x + xw4.x;
            float gf = p0.y + p1.y + xw4.y;
            float gc = p0.z + p1.z + xw4.z;
            float go = p0.w + p1.w + xw4.w;
            float it_ = 1.f / (1.f + __expf(-gi));
            float ft  = 1.f / (1.f + __expf(-gf));
            float ch  = tanhf(gc);
            float ot  = 1.f / (1.f + __expf(-go));
            float cn  = mr * (ft * cr + it_ * ch);
            cr = cn;
            float hn = ot * tanhf(cn);
            out[(size_t)t * BH + pidx] = hn;
            size_t nb = (size_t)((t + 1) & 1) * (BB * HH);
            __nv_bfloat16 hb = __float2bfloat16(hn);
            g_hBhi[nb + pidx] = hb;
            g_hBlo[nb + pidx] = __float2bfloat16(hn - __bfloat162float(hb));
        }

        __syncthreads();
        if (tid == 0) {
            __threadfence();
            atomicAdd(&g_ctr4[rg], 1u);
            unsigned target = (unsigned)(t + 1) * 32u;
            while (*(volatile unsigned*)&g_ctr4[rg] < target) { }
            __threadfence();
        }
        __syncthreads();
    }

    g_c[pidx] = cr;
}

// copy h_T (== outputs[S-1]) and c_T into the output tail
__global__ void finalize(float* __restrict__ out)
{
    int i = blockIdx.x * blockDim.x + threadIdx.x;
    if (i < BH) {
        out[(size_t)SS * BH + i]      = out[(size_t)(SS - 1) * BH + i];
        out[(size_t)SS * BH + BH + i] = g_c[i];
    }
}

// ---------------------------------------------------------------------------
extern "C" void kernel_launch(void* const* d_in, const int* in_sizes, int n_in,
                              void* d_out, int out_size)
{
    const float* x     = (const float*)d_in[0];
    const float* h0    = (const float*)d_in[1];
    const float* c0    = (const float*)d_in[2];
    const float* alpha = (const float*)d_in[3];
    const float* beta  = (const float*)d_in[4];
    const float* theta = (const float*)d_in[5];
    const float* tspan = (const float*)d_in[6];
    const float* A     = (const float*)d_in[7];
    const float* Bm    = (const float*)d_in[8];
    const float* C     = (const float*)d_in[9];
    const float* Wi = (const float*)d_in[10];
    const float* Ui = (const float*)d_in[11];
    const float* bi = (const float*)d_in[12];
    const float* Wf = (const float*)d_in[13];
    const float* Uf = (const float*)d_in[14];
    const float* bf = (const float*)d_in[15];
    const float* Wc = (const float*)d_in[16];
    const float* Uc = (const float*)d_in[17];
    const float* bc = (const float*)d_in[18];
    const float* Wo = (const float*)d_in[19];
    const float* Uo = (const float*)d_in[20];
    const float* bo = (const float*)d_in[21];
    float* out = (float*)d_out;

    const int SMEM  = (2 * 64 * ROWW + 2 * 32 * ROWW + 2 * 32 * 68) * 4;  // 217088 B
    const int XSMEM = 4 * 128 * ROWX * 4;                                  // 73728 B
    cudaFuncSetAttribute(lstm_persist, cudaFuncAttributeMaxDynamicSharedMemorySize, SMEM);
    cudaFuncSetAttribute(xw_mma, cudaFuncAttributeMaxDynamicSharedMemorySize, XSMEM);

    prep_weights<<<1024, 256>>>(Wi, Ui, bi, Wf, Uf, bf, Wc, Uc, bc, Wo, Uo, bo);
    mdhp_kernel<<<BB, 512>>>(alpha, beta, theta, tspan, A, Bm, C);
    prep_state<<<(BB * HH + 255) / 256, 256>>>(h0);
    xsplit<<<(SS * BB * DD / 4) / 256, 256>>>(x);
    xw_mma<<<dim3(GG / 128, (SS * BB) / 128), 256, XSMEM>>>();
    lstm_persist<<<dim3(32, 4), 512, SMEM>>>(c0, out);
    finalize<<<(BH + 255) / 256, 256>>>(out);
}